// round 15
// baseline (speedup 1.0000x reference)
#include <cuda_runtime.h>
#include <cstdint>

#define BH    64          // B*h
#define DIM   32          // d
#define LPIX  4096        // H*W
#define MM    64          // number of clusters (L_)
#define QK_SCALE 0.17677669529663687f

// ---- device scratch (no allocations allowed) ----
__device__ __align__(256) float g_cq0[BH * MM * DIM];        // 512 KB
__device__ __align__(256) float g_rpb0[LPIX * MM];           // 1 MB (input-independent)
__device__ __align__(256) unsigned char g_assign[BH * LPIX]; // 256 KB
__device__ __align__(256) unsigned short g_sorted[BH * LPIX];// 512 KB
__device__ __align__(256) int g_soff[BH * 65];               // 16.6 KB
__device__ __align__(256) float g_centers[BH * MM * 2];      // 32 KB
__device__ int g_ctr[BH];                                    // fan-in counters

__device__ __forceinline__ float sqrt_ap(float x) {
    float y; asm("sqrt.approx.f32 %0, %1;" : "=f"(y) : "f"(x)); return y;
}
__device__ __forceinline__ unsigned long long pack2(float lo, float hi) {
    unsigned long long r;
    asm("mov.b64 %0, {%1, %2};" : "=l"(r) : "f"(lo), "f"(hi));
    return r;
}
__device__ __forceinline__ void unpack2(unsigned long long v, float& lo, float& hi) {
    asm("mov.b64 {%0, %1}, %2;" : "=f"(lo), "=f"(hi) : "l"(v));
}
__device__ __forceinline__ void fma2(unsigned long long& d,
                                     unsigned long long a, unsigned long long b) {
    asm("fma.rn.f32x2 %0, %1, %2, %0;" : "+l"(d) : "l"(a), "l"(b));
}

// ---------------------------------------------------------------------------
// K01: fused init. Blocks [0,4096): c_q0 (window mean + l2norm).
//      Blocks [4096,4352): rpb0 table (input-independent) + counter reset.
// ---------------------------------------------------------------------------
__global__ void __launch_bounds__(256) k_init(const float* __restrict__ xk) {
    if (blockIdx.x < 4096) {
        int blk = blockIdx.x;
        int bh = blk >> 6, m = blk & 63;
        int wr = m >> 3, wc = m & 7;
        int warp = threadIdx.x >> 5, lane = threadIdx.x & 31;

        const float* row = xk + (size_t)bh * LPIX * DIM
                              + ((size_t)(wr * 8 + warp) * 64 + wc * 8) * DIM;
        float acc = 0.f;
#pragma unroll
        for (int k = 0; k < 8; k++) acc += row[k * 32 + lane];

        __shared__ float s[8][32];
        s[warp][lane] = acc;
        __syncthreads();
        if (warp == 0) {
            float v = 0.f;
#pragma unroll
            for (int w = 0; w < 8; w++) v += s[w][lane];
            v *= (1.0f / 64.0f);
            float sq = v * v;
#pragma unroll
            for (int o = 16; o > 0; o >>= 1) sq += __shfl_xor_sync(0xffffffffu, sq, o);
            float inv = 1.0f / fmaxf(sqrt_ap(sq), 1e-12f);
            g_cq0[((size_t)bh * 64 + m) * 32 + lane] = v * inv;
        }
    } else {
        if (blockIdx.x == 4096 && threadIdx.x < BH)
            g_ctr[threadIdx.x] = 0;                  // reset fan-in counters
        int idx = (blockIdx.x - 4096) * 256 + threadIdx.x;  // over LPIX*MM/4
        int m0 = (idx & 15) * 4;
        int l  = idx >> 4;
        float fi = (float)(l >> 6), fj = (float)(l & 63);
        float4 r;
        float* rp = &r.x;
#pragma unroll
        for (int q = 0; q < 4; q++) {
            int m = m0 + q;
            float ch = (float)((m >> 3) << 3) + 3.5f;
            float cw = (float)((m & 7) << 3) + 3.5f;
            float dh = fi - ch, dw = fj - cw;
            rp[q] = __expf(-sqrt_ap(dh * dh + dw * dw));
        }
        ((float4*)g_rpb0)[idx] = r;
    }
}

// ---------------------------------------------------------------------------
// K2a: per-pixel argmax (packed fma.rn.f32x2) + FAN-IN SORT: the last block
// of each bh (16 blocks/bh) runs the deterministic counting sort for that bh.
// ---------------------------------------------------------------------------
__global__ void __launch_bounds__(256) k_assign(const float* __restrict__ xk,
                                                const float* __restrict__ scale) {
    int bh = blockIdx.y;
    int l  = blockIdx.x * 256 + threadIdx.x;
    int warp = threadIdx.x >> 5, lane = threadIdx.x & 31;

    __shared__ __align__(16) ulonglong2 sct[32][16];   // 8 KB
    const float* cq = g_cq0 + (size_t)bh * (MM * DIM);
#pragma unroll
    for (int t = threadIdx.x; t < 512; t += 256) {
        int k = t >> 4, mq = t & 15;
        float c0 = cq[(4 * mq + 0) * 32 + k];
        float c1 = cq[(4 * mq + 1) * 32 + k];
        float c2 = cq[(4 * mq + 2) * 32 + k];
        float c3 = cq[(4 * mq + 3) * 32 + k];
        sct[k][mq] = make_ulonglong2(pack2(c0, c1), pack2(c2, c3));
    }
    __syncthreads();

    float qs = QK_SCALE * scale[0];
    unsigned long long xx[32];           // (x_k, x_k) duplicated pairs
    const float4* xr = (const float4*)(xk + (size_t)bh * LPIX * DIM + (size_t)l * DIM);
#pragma unroll
    for (int k8 = 0; k8 < 8; k8++) {
        float4 v = xr[k8];
        float x0 = v.x * qs, x1 = v.y * qs, x2 = v.z * qs, x3 = v.w * qs;
        xx[4 * k8 + 0] = pack2(x0, x0);
        xx[4 * k8 + 1] = pack2(x1, x1);
        xx[4 * k8 + 2] = pack2(x2, x2);
        xx[4 * k8 + 3] = pack2(x3, x3);
    }

    const float4* rp = (const float4*)(g_rpb0 + (size_t)l * MM);
    float maxv = -1e30f;
    int argm = 0;
    for (int mq = 0; mq < 16; mq++) {
        float4 rb = rp[mq];
        unsigned long long acc01 = pack2(rb.x, rb.y);
        unsigned long long acc23 = pack2(rb.z, rb.w);
#pragma unroll
        for (int k = 0; k < 32; k++) {
            ulonglong2 c = sct[k][mq];
            fma2(acc01, xx[k], c.x);
            fma2(acc23, xx[k], c.y);
        }
        float a0, a1, a2, a3;
        unpack2(acc01, a0, a1);
        unpack2(acc23, a2, a3);
        // first-argmax semantics (ascending m)
        if (a0 > maxv) { maxv = a0; argm = 4 * mq + 0; }
        if (a1 > maxv) { maxv = a1; argm = 4 * mq + 1; }
        if (a2 > maxv) { maxv = a2; argm = 4 * mq + 2; }
        if (a3 > maxv) { maxv = a3; argm = 4 * mq + 3; }
    }
    g_assign[(size_t)bh * LPIX + l] = (unsigned char)argm;

    // ================= fan-in: last block of this bh sorts it ===============
    __shared__ int s_last;
    __threadfence();                      // release our g_assign writes
    __syncthreads();
    if (threadIdx.x == 0)
        s_last = (atomicAdd(&g_ctr[bh], 1) == 15) ? 1 : 0;
    __syncthreads();
    if (!s_last) return;
    __threadfence();                      // acquire other blocks' writes

    // ---- 256-thread deterministic counting sort for this bh ----
    __shared__ __align__(16) unsigned char sa[LPIX];        // 4 KB
    __shared__ __align__(16) unsigned short slist[LPIX];    // 8 KB
    __shared__ __align__(16) int shist[8][65];              // padded
    __shared__ __align__(16) int scur[8][65];
    __shared__ __align__(16) int stot[64];
    __shared__ __align__(16) int soff[65];

    ((uint4*)sa)[threadIdx.x] = ((const uint4*)(g_assign + (size_t)bh * LPIX))[threadIdx.x];
    for (int i = threadIdx.x; i < 8 * 65; i += 256) ((int*)shist)[i] = 0;
    __syncthreads();

    // per-warp histogram: warp w owns px [w*512,(w+1)*512), 16 iters
    int mloc[16];
    int base = warp * 512;
#pragma unroll
    for (int it = 0; it < 16; ++it) {
        int m = sa[base + it * 32 + lane];
        mloc[it] = m;
        unsigned int grp = __match_any_sync(0xffffffffu, m);
        int leader = __ffs(grp) - 1;
        if (lane == leader) shist[warp][m] += __popc(grp);
    }
    __syncthreads();

    // per-cluster totals + per-warp starts (64 threads, 8-step chains)
    if (threadIdx.x < 64) {
        int run = 0;
#pragma unroll
        for (int w = 0; w < 8; w++) { scur[w][threadIdx.x] = run; run += shist[w][threadIdx.x]; }
        stot[threadIdx.x] = run;
    }
    __syncthreads();

    // exclusive prefix over 64 cluster totals (single warp shuffle scan)
    if (warp == 0) {
        int v0 = stot[2 * lane], v1 = stot[2 * lane + 1];
        int s = v0 + v1;
#pragma unroll
        for (int o = 1; o < 32; o <<= 1) {
            int t = __shfl_up_sync(0xffffffffu, s, o);
            if (lane >= o) s += t;
        }
        int excl = s - v0 - v1;
        soff[2 * lane]     = excl;
        soff[2 * lane + 1] = excl + v0;
        if (lane == 31) soff[64] = s;      // == LPIX
    }
    __syncthreads();

    // cursors += cluster base (512 entries, parallel)
    {
        int p0 = threadIdx.x;              // (w = p>>6, m = p&63)
        scur[p0 >> 6][p0 & 63] += soff[p0 & 63];
        int p1 = threadIdx.x + 256;
        scur[p1 >> 6][p1 & 63] += soff[p1 & 63];
    }
    __syncthreads();

    // stable scatter into shared slist (16 iters)
    unsigned int ltmask = (1u << lane) - 1u;
#pragma unroll
    for (int it = 0; it < 16; ++it) {
        int m = mloc[it];
        unsigned int grp = __match_any_sync(0xffffffffu, m);
        int rank = __popc(grp & ltmask);
        int pos = scur[warp][m];
        slist[pos + rank] = (unsigned short)(base + it * 32 + lane);
        int leader = __ffs(grp) - 1;
        if (lane == leader) scur[warp][m] = pos + __popc(grp);
        __syncwarp();
    }
    __syncthreads();

    // coalesced copy to global: 256 threads x 4 uint2 = 8 KB
    uint2* gs = (uint2*)(g_sorted + (size_t)bh * LPIX);
    const uint2* ss = (const uint2*)slist;
#pragma unroll
    for (int i = 0; i < 4; i++)
        gs[threadIdx.x + i * 256] = ss[threadIdx.x + i * 256];

    if (threadIdx.x < 65) g_soff[bh * 65 + threadIdx.x] = soff[threadIdx.x];
}

// ---------------------------------------------------------------------------
// K2b: pure gather from presorted lists. Block per (bh,m), 128 threads.
// 4 warps chunk the list; 4 entries/iter -> 8 outstanding 128B loads.
// ---------------------------------------------------------------------------
__global__ void __launch_bounds__(128) k_gather(const float* __restrict__ xk,
                                                const float* __restrict__ xv,
                                                float* __restrict__ out) {
    int blk = blockIdx.x;
    int bh = blk >> 6, m = blk & 63;
    int warp = threadIdx.x >> 5, lane = threadIdx.x & 31;

    int s0 = g_soff[bh * 65 + m];
    int n  = g_soff[bh * 65 + m + 1] - s0;
    const unsigned short* lst = g_sorted + (size_t)bh * LPIX + s0;

    const float* xkb = xk + (size_t)bh * LPIX * DIM;
    const float* xvb = xv + (size_t)bh * LPIX * DIM;

    float accK = 0.f, accV = 0.f;
    int isi = 0, isj = 0;
    int per = (n + 3) >> 2;
    int e  = warp * per;
    int e1 = min(e + per, n);
    for (; e + 3 < e1; e += 4) {
        int l0 = lst[e], l1 = lst[e + 1], l2 = lst[e + 2], l3 = lst[e + 3];
        float k0 = __ldg(xkb + l0 * 32 + lane);
        float k1 = __ldg(xkb + l1 * 32 + lane);
        float k2 = __ldg(xkb + l2 * 32 + lane);
        float k3 = __ldg(xkb + l3 * 32 + lane);
        float v0 = __ldg(xvb + l0 * 32 + lane);
        float v1 = __ldg(xvb + l1 * 32 + lane);
        float v2 = __ldg(xvb + l2 * 32 + lane);
        float v3 = __ldg(xvb + l3 * 32 + lane);
        accK += (k0 + k1) + (k2 + k3);
        accV += (v0 + v1) + (v2 + v3);
        isi += (l0 >> 6) + (l1 >> 6) + (l2 >> 6) + (l3 >> 6);
        isj += (l0 & 63) + (l1 & 63) + (l2 & 63) + (l3 & 63);
    }
    for (; e < e1; ++e) {
        int l0 = lst[e];
        accK += __ldg(xkb + l0 * 32 + lane);
        accV += __ldg(xvb + l0 * 32 + lane);
        isi += l0 >> 6;
        isj += l0 & 63;
    }

    __shared__ float sk[4][32], sv[4][32];
    __shared__ int ssi[4], ssj[4];
    sk[warp][lane] = accK;
    sv[warp][lane] = accV;
    if (lane == 0) { ssi[warp] = isi; ssj[warp] = isj; }
    __syncthreads();

    if (warp == 0) {
        float k4 = sk[0][lane] + sk[1][lane] + sk[2][lane] + sk[3][lane];
        float v4 = sv[0][lane] + sv[1][lane] + sv[2][lane] + sv[3][lane];
        float tsi = (float)(ssi[0] + ssi[1] + ssi[2] + ssi[3]);
        float tsj = (float)(ssj[0] + ssj[1] + ssj[2] + ssj[3]);
        float denom = (n > 0) ? (float)n : 1.0f;   // matches s==0 -> 1 guard

        if (lane == 0) {
            g_centers[((size_t)bh * 64 + m) * 2 + 0] = tsi / denom;
            g_centers[((size_t)bh * 64 + m) * 2 + 1] = tsj / denom;
        }
        out[131072 + ((size_t)bh * 64 + m) * 32 + lane] = v4 / denom;  // c_v
        float sq = k4 * k4;
#pragma unroll
        for (int o = 16; o > 0; o >>= 1) sq += __shfl_xor_sync(0xffffffffu, sq, o);
        float inv = 1.0f / fmaxf(sqrt_ap(sq), 1e-12f);
        out[((size_t)bh * 64 + m) * 32 + lane] = k4 * inv;             // c_q
    }
}

// ---------------------------------------------------------------------------
// K3: rpb[bh][l][m] = exp(-dist(pixel l, center[bh][m])); streaming stores
// ---------------------------------------------------------------------------
__global__ void __launch_bounds__(256) k_rpb(float* __restrict__ out) {
    int bh = blockIdx.y;
    __shared__ float2 sc[MM];
    if (threadIdx.x < 64)
        sc[threadIdx.x] = ((const float2*)(g_centers + (size_t)bh * 128))[threadIdx.x];
    __syncthreads();

    int pix = threadIdx.x >> 4;     // 0..15
    int mg  = threadIdx.x & 15;     // 0..15 (quad of m)
    int l = blockIdx.x * 16 + pix;
    float fi = (float)(l >> 6), fj = (float)(l & 63);
    float4 r;
#pragma unroll
    for (int q = 0; q < 4; q++) {
        float2 c = sc[mg * 4 + q];
        float dh = fi - c.x, dw = fj - c.y;
        (&r.x)[q] = __expf(-sqrt_ap(dh * dh + dw * dw));
    }
    __stcs((float4*)(out + 262144) + (size_t)bh * 65536 + (size_t)l * 16 + mg, r);
}

// ---------------------------------------------------------------------------
extern "C" void kernel_launch(void* const* d_in, const int* in_sizes, int n_in,
                              void* d_out, int out_size) {
    const float* xk    = (const float*)d_in[0];
    const float* xv    = (const float*)d_in[1];
    const float* scale = (const float*)d_in[2];
    float* out = (float*)d_out;

    k_init<<<4352, 256>>>(xk);
    dim3 g2(16, 64);
    k_assign<<<g2, 256>>>(xk, scale);
    k_gather<<<4096, 128>>>(xk, xv, out);
    dim3 g3(256, 64);
    k_rpb<<<g3, 256>>>(out);
}

// round 16
// speedup vs baseline: 1.0859x; 1.0859x over previous
#include <cuda_runtime.h>
#include <cstdint>

#define BH    64          // B*h
#define DIM   32          // d
#define LPIX  4096        // H*W
#define MM    64          // number of clusters (L_)
#define QK_SCALE 0.17677669529663687f

#define GDC_WAIT()   asm volatile("griddepcontrol.wait;" ::: "memory")
#define GDC_LAUNCH() asm volatile("griddepcontrol.launch_dependents;")

// ---- device scratch (no allocations allowed) ----
__device__ __align__(256) float g_cq0[BH * MM * DIM];        // 512 KB
__device__ __align__(256) float g_rpb0[LPIX * MM];           // 1 MB (input-independent)
__device__ __align__(256) unsigned char g_assign[BH * LPIX]; // 256 KB
__device__ __align__(256) unsigned short g_sorted[BH * LPIX];// 512 KB
__device__ __align__(256) int g_soff[BH * 65];               // 16.6 KB
__device__ __align__(256) float g_centers[BH * MM * 2];      // 32 KB

__device__ __forceinline__ float sqrt_ap(float x) {
    float y; asm("sqrt.approx.f32 %0, %1;" : "=f"(y) : "f"(x)); return y;
}
__device__ __forceinline__ unsigned long long pack2(float lo, float hi) {
    unsigned long long r;
    asm("mov.b64 %0, {%1, %2};" : "=l"(r) : "f"(lo), "f"(hi));
    return r;
}
__device__ __forceinline__ void unpack2(unsigned long long v, float& lo, float& hi) {
    asm("mov.b64 {%0, %1}, %2;" : "=f"(lo), "=f"(hi) : "l"(v));
}
__device__ __forceinline__ void fma2(unsigned long long& d,
                                     unsigned long long a, unsigned long long b) {
    asm("fma.rn.f32x2 %0, %1, %2, %0;" : "+l"(d) : "l"(a), "l"(b));
}

// ---------------------------------------------------------------------------
// K01: fused init. Blocks [0,4096): c_q0 (window mean + l2norm).
//      Blocks [4096,4352): rpb0 table (input-independent).
// ---------------------------------------------------------------------------
__global__ void __launch_bounds__(256) k_init(const float* __restrict__ xk) {
    GDC_LAUNCH();
    if (blockIdx.x < 4096) {
        int blk = blockIdx.x;
        int bh = blk >> 6, m = blk & 63;
        int wr = m >> 3, wc = m & 7;
        int warp = threadIdx.x >> 5, lane = threadIdx.x & 31;

        const float* row = xk + (size_t)bh * LPIX * DIM
                              + ((size_t)(wr * 8 + warp) * 64 + wc * 8) * DIM;
        float acc = 0.f;
#pragma unroll
        for (int k = 0; k < 8; k++) acc += row[k * 32 + lane];

        __shared__ float s[8][32];
        s[warp][lane] = acc;
        __syncthreads();
        if (warp == 0) {
            float v = 0.f;
#pragma unroll
            for (int w = 0; w < 8; w++) v += s[w][lane];
            v *= (1.0f / 64.0f);
            float sq = v * v;
#pragma unroll
            for (int o = 16; o > 0; o >>= 1) sq += __shfl_xor_sync(0xffffffffu, sq, o);
            float inv = 1.0f / fmaxf(sqrt_ap(sq), 1e-12f);
            g_cq0[((size_t)bh * 64 + m) * 32 + lane] = v * inv;
        }
    } else {
        int idx = (blockIdx.x - 4096) * 256 + threadIdx.x;  // over LPIX*MM/4
        int m0 = (idx & 15) * 4;
        int l  = idx >> 4;
        float fi = (float)(l >> 6), fj = (float)(l & 63);
        float4 r;
        float* rp = &r.x;
#pragma unroll
        for (int q = 0; q < 4; q++) {
            int m = m0 + q;
            float ch = (float)((m >> 3) << 3) + 3.5f;
            float cw = (float)((m & 7) << 3) + 3.5f;
            float dh = fi - ch, dw = fj - cw;
            rp[q] = __expf(-sqrt_ap(dh * dh + dw * dw));
        }
        ((float4*)g_rpb0)[idx] = r;
    }
}

// ---------------------------------------------------------------------------
// K2a: per-pixel argmax using packed fma.rn.f32x2 (2 MACs/instr).
// ---------------------------------------------------------------------------
__global__ void __launch_bounds__(256) k_assign(const float* __restrict__ xk,
                                                const float* __restrict__ scale) {
    GDC_WAIT();        // g_cq0 / g_rpb0 from k_init
    GDC_LAUNCH();
    int bh = blockIdx.y;
    int l  = blockIdx.x * 256 + threadIdx.x;

    __shared__ __align__(16) ulonglong2 sct[32][16];   // 8 KB
    const float* cq = g_cq0 + (size_t)bh * (MM * DIM);
#pragma unroll
    for (int t = threadIdx.x; t < 512; t += 256) {
        int k = t >> 4, mq = t & 15;
        float c0 = cq[(4 * mq + 0) * 32 + k];
        float c1 = cq[(4 * mq + 1) * 32 + k];
        float c2 = cq[(4 * mq + 2) * 32 + k];
        float c3 = cq[(4 * mq + 3) * 32 + k];
        sct[k][mq] = make_ulonglong2(pack2(c0, c1), pack2(c2, c3));
    }
    __syncthreads();

    float qs = QK_SCALE * scale[0];
    unsigned long long xx[32];           // (x_k, x_k) duplicated pairs
    const float4* xr = (const float4*)(xk + (size_t)bh * LPIX * DIM + (size_t)l * DIM);
#pragma unroll
    for (int k8 = 0; k8 < 8; k8++) {
        float4 v = xr[k8];
        float x0 = v.x * qs, x1 = v.y * qs, x2 = v.z * qs, x3 = v.w * qs;
        xx[4 * k8 + 0] = pack2(x0, x0);
        xx[4 * k8 + 1] = pack2(x1, x1);
        xx[4 * k8 + 2] = pack2(x2, x2);
        xx[4 * k8 + 3] = pack2(x3, x3);
    }

    const float4* rp = (const float4*)(g_rpb0 + (size_t)l * MM);
    float maxv = -1e30f;
    int argm = 0;
    for (int mq = 0; mq < 16; mq++) {
        float4 rb = rp[mq];
        unsigned long long acc01 = pack2(rb.x, rb.y);
        unsigned long long acc23 = pack2(rb.z, rb.w);
#pragma unroll
        for (int k = 0; k < 32; k++) {
            ulonglong2 c = sct[k][mq];
            fma2(acc01, xx[k], c.x);
            fma2(acc23, xx[k], c.y);
        }
        float a0, a1, a2, a3;
        unpack2(acc01, a0, a1);
        unpack2(acc23, a2, a3);
        // first-argmax semantics (ascending m)
        if (a0 > maxv) { maxv = a0; argm = 4 * mq + 0; }
        if (a1 > maxv) { maxv = a1; argm = 4 * mq + 1; }
        if (a2 > maxv) { maxv = a2; argm = 4 * mq + 2; }
        if (a3 > maxv) { maxv = a3; argm = 4 * mq + 3; }
    }
    g_assign[(size_t)bh * LPIX + l] = (unsigned char)argm;
}

// ---------------------------------------------------------------------------
// K2s: deterministic counting sort, per bh. 1024 threads (32 warps).
// Scatter to SHARED slist, then coalesced uint2 copy to global.
// ---------------------------------------------------------------------------
__global__ void __launch_bounds__(1024) k_sort() {
    GDC_WAIT();        // g_assign from k_assign
    GDC_LAUNCH();
    int bh = blockIdx.x;
    int tid = threadIdx.x;
    int warp = tid >> 5, lane = tid & 31;

    __shared__ __align__(16) unsigned char sa[LPIX];     // 4 KB
    __shared__ __align__(16) unsigned short slist[LPIX]; // 8 KB
    __shared__ int shist[32][65];          // padded: conflict-free cols
    __shared__ int scur[32][65];
    __shared__ int stot[64];
    __shared__ int soff[65];

    ((uint*)sa)[tid] = ((const uint*)(g_assign + (size_t)bh * LPIX))[tid];
    shist[warp][lane] = 0;
    shist[warp][lane + 32] = 0;
    __syncthreads();

    // ---- per-warp histogram (4 iterations of 32 pixels)
    int mloc[4];
    int base = warp * 128;
#pragma unroll
    for (int it = 0; it < 4; ++it) {
        int m = sa[base + it * 32 + lane];
        mloc[it] = m;
        unsigned int grp = __match_any_sync(0xffffffffu, m);
        int leader = __ffs(grp) - 1;
        if (lane == leader) shist[warp][m] += __popc(grp);
    }
    __syncthreads();

    // ---- warp-parallel combine: warp handles clusters {warp, warp+32}
#pragma unroll
    for (int c = 0; c < 2; c++) {
        int m = warp + c * 32;
        int v = shist[lane][m];
        int s = v;
#pragma unroll
        for (int o = 1; o < 32; o <<= 1) {
            int t = __shfl_up_sync(0xffffffffu, s, o);
            if (lane >= o) s += t;
        }
        scur[lane][m] = s - v;             // exclusive over warps
        if (lane == 31) stot[m] = s;
    }
    __syncthreads();

    // ---- exclusive prefix over 64 cluster totals (single warp)
    if (warp == 0) {
        int v0 = stot[2 * lane], v1 = stot[2 * lane + 1];
        int s = v0 + v1;
#pragma unroll
        for (int o = 1; o < 32; o <<= 1) {
            int t = __shfl_up_sync(0xffffffffu, s, o);
            if (lane >= o) s += t;
        }
        int excl = s - v0 - v1;
        soff[2 * lane]     = excl;
        soff[2 * lane + 1] = excl + v0;
        if (lane == 31) soff[64] = s;      // == LPIX
    }
    __syncthreads();

    // ---- cursors += cluster base (fully parallel)
    {
        int p0 = tid;
        scur[p0 >> 6][p0 & 63] += soff[p0 & 63];
        int p1 = tid + 1024;
        scur[p1 >> 6][p1 & 63] += soff[p1 & 63];
    }
    __syncthreads();

    // ---- stable scatter into SHARED slist (4 iterations)
    unsigned int ltmask = (1u << lane) - 1u;
#pragma unroll
    for (int it = 0; it < 4; ++it) {
        int m = mloc[it];
        unsigned int grp = __match_any_sync(0xffffffffu, m);
        int rank = __popc(grp & ltmask);
        int pos = scur[warp][m];
        slist[pos + rank] = (unsigned short)(base + it * 32 + lane);
        int leader = __ffs(grp) - 1;
        if (lane == leader) scur[warp][m] = pos + __popc(grp);
        __syncwarp();
    }
    __syncthreads();

    // ---- coalesced copy to global: 1024 threads x 8B = 8 KB
    ((uint2*)(g_sorted + (size_t)bh * LPIX))[tid] = ((const uint2*)slist)[tid];

    if (tid < 65) g_soff[bh * 65 + tid] = soff[tid];
}

// ---------------------------------------------------------------------------
// K2b: pure gather from presorted lists. Block per (bh,m), 128 threads.
// 4 warps chunk the list; 4 entries/iter -> 8 outstanding 128B loads.
// ---------------------------------------------------------------------------
__global__ void __launch_bounds__(128) k_gather(const float* __restrict__ xk,
                                                const float* __restrict__ xv,
                                                float* __restrict__ out) {
    GDC_WAIT();        // g_sorted / g_soff from k_sort
    GDC_LAUNCH();
    int blk = blockIdx.x;
    int bh = blk >> 6, m = blk & 63;
    int warp = threadIdx.x >> 5, lane = threadIdx.x & 31;

    int s0 = g_soff[bh * 65 + m];
    int n  = g_soff[bh * 65 + m + 1] - s0;
    const unsigned short* lst = g_sorted + (size_t)bh * LPIX + s0;

    const float* xkb = xk + (size_t)bh * LPIX * DIM;
    const float* xvb = xv + (size_t)bh * LPIX * DIM;

    float accK = 0.f, accV = 0.f;
    int isi = 0, isj = 0;
    int per = (n + 3) >> 2;
    int e  = warp * per;
    int e1 = min(e + per, n);
    for (; e + 3 < e1; e += 4) {
        int l0 = lst[e], l1 = lst[e + 1], l2 = lst[e + 2], l3 = lst[e + 3];
        float k0 = __ldg(xkb + l0 * 32 + lane);
        float k1 = __ldg(xkb + l1 * 32 + lane);
        float k2 = __ldg(xkb + l2 * 32 + lane);
        float k3 = __ldg(xkb + l3 * 32 + lane);
        float v0 = __ldg(xvb + l0 * 32 + lane);
        float v1 = __ldg(xvb + l1 * 32 + lane);
        float v2 = __ldg(xvb + l2 * 32 + lane);
        float v3 = __ldg(xvb + l3 * 32 + lane);
        accK += (k0 + k1) + (k2 + k3);
        accV += (v0 + v1) + (v2 + v3);
        isi += (l0 >> 6) + (l1 >> 6) + (l2 >> 6) + (l3 >> 6);
        isj += (l0 & 63) + (l1 & 63) + (l2 & 63) + (l3 & 63);
    }
    for (; e < e1; ++e) {
        int l0 = lst[e];
        accK += __ldg(xkb + l0 * 32 + lane);
        accV += __ldg(xvb + l0 * 32 + lane);
        isi += l0 >> 6;
        isj += l0 & 63;
    }

    __shared__ float sk[4][32], sv[4][32];
    __shared__ int ssi[4], ssj[4];
    sk[warp][lane] = accK;
    sv[warp][lane] = accV;
    if (lane == 0) { ssi[warp] = isi; ssj[warp] = isj; }
    __syncthreads();

    if (warp == 0) {
        float k4 = sk[0][lane] + sk[1][lane] + sk[2][lane] + sk[3][lane];
        float v4 = sv[0][lane] + sv[1][lane] + sv[2][lane] + sv[3][lane];
        float tsi = (float)(ssi[0] + ssi[1] + ssi[2] + ssi[3]);
        float tsj = (float)(ssj[0] + ssj[1] + ssj[2] + ssj[3]);
        float denom = (n > 0) ? (float)n : 1.0f;   // matches s==0 -> 1 guard

        if (lane == 0) {
            g_centers[((size_t)bh * 64 + m) * 2 + 0] = tsi / denom;
            g_centers[((size_t)bh * 64 + m) * 2 + 1] = tsj / denom;
        }
        out[131072 + ((size_t)bh * 64 + m) * 32 + lane] = v4 / denom;  // c_v
        float sq = k4 * k4;
#pragma unroll
        for (int o = 16; o > 0; o >>= 1) sq += __shfl_xor_sync(0xffffffffu, sq, o);
        float inv = 1.0f / fmaxf(sqrt_ap(sq), 1e-12f);
        out[((size_t)bh * 64 + m) * 32 + lane] = k4 * inv;             // c_q
    }
}

// ---------------------------------------------------------------------------
// K3: rpb[bh][l][m] = exp(-dist(pixel l, center[bh][m])); streaming stores
// ---------------------------------------------------------------------------
__global__ void __launch_bounds__(256) k_rpb(float* __restrict__ out) {
    GDC_WAIT();        // g_centers from k_gather
    int bh = blockIdx.y;
    __shared__ float2 sc[MM];
    if (threadIdx.x < 64)
        sc[threadIdx.x] = ((const float2*)(g_centers + (size_t)bh * 128))[threadIdx.x];
    __syncthreads();

    int pix = threadIdx.x >> 4;     // 0..15
    int mg  = threadIdx.x & 15;     // 0..15 (quad of m)
    int l = blockIdx.x * 16 + pix;
    float fi = (float)(l >> 6), fj = (float)(l & 63);
    float4 r;
#pragma unroll
    for (int q = 0; q < 4; q++) {
        float2 c = sc[mg * 4 + q];
        float dh = fi - c.x, dw = fj - c.y;
        (&r.x)[q] = __expf(-sqrt_ap(dh * dh + dw * dw));
    }
    __stcs((float4*)(out + 262144) + (size_t)bh * 65536 + (size_t)l * 16 + mg, r);
}

// ---------------------------------------------------------------------------
static inline void launch_pdl(void* fn, dim3 grid, dim3 block,
                              void** args, cudaStream_t stream) {
    cudaLaunchConfig_t cfg = {};
    cudaLaunchAttribute attr[1];
    attr[0].id = cudaLaunchAttributeProgrammaticStreamSerialization;
    attr[0].val.programmaticStreamSerializationAllowed = 1;
    cfg.gridDim = grid;
    cfg.blockDim = block;
    cfg.attrs = attr;
    cfg.numAttrs = 1;
    cfg.stream = stream;
    cudaLaunchKernelExC(&cfg, fn, args);
}

extern "C" void kernel_launch(void* const* d_in, const int* in_sizes, int n_in,
                              void* d_out, int out_size) {
    const float* xk    = (const float*)d_in[0];
    const float* xv    = (const float*)d_in[1];
    const float* scale = (const float*)d_in[2];
    float* out = (float*)d_out;

    k_init<<<4352, 256>>>(xk);

    {
        void* args[] = { (void*)&xk, (void*)&scale };
        launch_pdl((void*)k_assign, dim3(16, 64), dim3(256), args, 0);
    }
    {
        void* args[] = {};
        launch_pdl((void*)k_sort, dim3(64), dim3(1024), args, 0);
    }
    {
        void* args[] = { (void*)&xk, (void*)&xv, (void*)&out };
        launch_pdl((void*)k_gather, dim3(4096), dim3(128), args, 0);
    }
    {
        void* args[] = { (void*)&out };
        launch_pdl((void*)k_rpb, dim3(256, 64), dim3(256), args, 0);
    }
}

// round 17
// speedup vs baseline: 1.0951x; 1.0084x over previous
#include <cuda_runtime.h>
#include <cstdint>

#define BH    64          // B*h
#define DIM   32          // d
#define LPIX  4096        // H*W
#define MM    64          // number of clusters (L_)
#define QK_SCALE 0.17677669529663687f

#define GDC_WAIT()   asm volatile("griddepcontrol.wait;" ::: "memory")
#define GDC_LAUNCH() asm volatile("griddepcontrol.launch_dependents;")

// ---- device scratch (no allocations allowed) ----
__device__ __align__(256) float g_cq0[BH * MM * DIM];        // 512 KB
__device__ __align__(256) float g_rpb0[LPIX * MM];           // 1 MB (input-independent)
__device__ __align__(256) unsigned char g_assign[BH * LPIX]; // 256 KB
__device__ __align__(256) unsigned short g_sorted[BH * LPIX];// 512 KB
__device__ __align__(256) int g_soff[BH * 65];               // 16.6 KB
__device__ __align__(256) float g_centers[BH * MM * 2];      // 32 KB

__device__ __forceinline__ float sqrt_ap(float x) {
    float y; asm("sqrt.approx.f32 %0, %1;" : "=f"(y) : "f"(x)); return y;
}
__device__ __forceinline__ unsigned long long pack2(float lo, float hi) {
    unsigned long long r;
    asm("mov.b64 %0, {%1, %2};" : "=l"(r) : "f"(lo), "f"(hi));
    return r;
}
__device__ __forceinline__ void unpack2(unsigned long long v, float& lo, float& hi) {
    asm("mov.b64 {%0, %1}, %2;" : "=f"(lo), "=f"(hi) : "l"(v));
}
__device__ __forceinline__ void fma2(unsigned long long& d,
                                     unsigned long long a, unsigned long long b) {
    asm("fma.rn.f32x2 %0, %1, %2, %0;" : "+l"(d) : "l"(a), "l"(b));
}

// ---------------------------------------------------------------------------
// K01: fused init. Blocks [0,4096): c_q0 (window mean + l2norm).
//      Blocks [4096,4352): rpb0 table (input-independent).
// ---------------------------------------------------------------------------
__global__ void __launch_bounds__(256) k_init(const float* __restrict__ xk) {
    GDC_LAUNCH();
    if (blockIdx.x < 4096) {
        int blk = blockIdx.x;
        int bh = blk >> 6, m = blk & 63;
        int wr = m >> 3, wc = m & 7;
        int warp = threadIdx.x >> 5, lane = threadIdx.x & 31;

        const float* row = xk + (size_t)bh * LPIX * DIM
                              + ((size_t)(wr * 8 + warp) * 64 + wc * 8) * DIM;
        float acc = 0.f;
#pragma unroll
        for (int k = 0; k < 8; k++) acc += row[k * 32 + lane];

        __shared__ float s[8][32];
        s[warp][lane] = acc;
        __syncthreads();
        if (warp == 0) {
            float v = 0.f;
#pragma unroll
            for (int w = 0; w < 8; w++) v += s[w][lane];
            v *= (1.0f / 64.0f);
            float sq = v * v;
#pragma unroll
            for (int o = 16; o > 0; o >>= 1) sq += __shfl_xor_sync(0xffffffffu, sq, o);
            float inv = 1.0f / fmaxf(sqrt_ap(sq), 1e-12f);
            g_cq0[((size_t)bh * 64 + m) * 32 + lane] = v * inv;
        }
    } else {
        int idx = (blockIdx.x - 4096) * 256 + threadIdx.x;  // over LPIX*MM/4
        int m0 = (idx & 15) * 4;
        int l  = idx >> 4;
        float fi = (float)(l >> 6), fj = (float)(l & 63);
        float4 r;
        float* rp = &r.x;
#pragma unroll
        for (int q = 0; q < 4; q++) {
            int m = m0 + q;
            float ch = (float)((m >> 3) << 3) + 3.5f;
            float cw = (float)((m & 7) << 3) + 3.5f;
            float dh = fi - ch, dw = fj - cw;
            rp[q] = __expf(-sqrt_ap(dh * dh + dw * dw));
        }
        ((float4*)g_rpb0)[idx] = r;
    }
}

// ---------------------------------------------------------------------------
// K2a: per-pixel argmax using packed fma.rn.f32x2 (2 MACs/instr).
// PDL: prefetch this pixel's x_k vector + scale (input-only, independent of
// k_init) BEFORE griddepcontrol.wait, so early-launched blocks overlap their
// DRAM fetch with k_init's tail.
// ---------------------------------------------------------------------------
__global__ void __launch_bounds__(256) k_assign(const float* __restrict__ xk,
                                                const float* __restrict__ scale) {
    int bh = blockIdx.y;
    int l  = blockIdx.x * 256 + threadIdx.x;

    // ---- independent prefetch (before the PDL wait) ----
    const float4* xr = (const float4*)(xk + (size_t)bh * LPIX * DIM + (size_t)l * DIM);
    float4 xp[8];
#pragma unroll
    for (int k8 = 0; k8 < 8; k8++) xp[k8] = xr[k8];
    float sc_raw = scale[0];

    GDC_WAIT();        // g_cq0 / g_rpb0 from k_init
    GDC_LAUNCH();

    __shared__ __align__(16) ulonglong2 sct[32][16];   // 8 KB
    const float* cq = g_cq0 + (size_t)bh * (MM * DIM);
#pragma unroll
    for (int t = threadIdx.x; t < 512; t += 256) {
        int k = t >> 4, mq = t & 15;
        float c0 = cq[(4 * mq + 0) * 32 + k];
        float c1 = cq[(4 * mq + 1) * 32 + k];
        float c2 = cq[(4 * mq + 2) * 32 + k];
        float c3 = cq[(4 * mq + 3) * 32 + k];
        sct[k][mq] = make_ulonglong2(pack2(c0, c1), pack2(c2, c3));
    }
    __syncthreads();

    float qs = QK_SCALE * sc_raw;
    unsigned long long xx[32];           // (x_k, x_k) duplicated pairs
#pragma unroll
    for (int k8 = 0; k8 < 8; k8++) {
        float4 v = xp[k8];
        float x0 = v.x * qs, x1 = v.y * qs, x2 = v.z * qs, x3 = v.w * qs;
        xx[4 * k8 + 0] = pack2(x0, x0);
        xx[4 * k8 + 1] = pack2(x1, x1);
        xx[4 * k8 + 2] = pack2(x2, x2);
        xx[4 * k8 + 3] = pack2(x3, x3);
    }

    const float4* rp = (const float4*)(g_rpb0 + (size_t)l * MM);
    float maxv = -1e30f;
    int argm = 0;
    for (int mq = 0; mq < 16; mq++) {
        float4 rb = rp[mq];
        unsigned long long acc01 = pack2(rb.x, rb.y);
        unsigned long long acc23 = pack2(rb.z, rb.w);
#pragma unroll
        for (int k = 0; k < 32; k++) {
            ulonglong2 c = sct[k][mq];
            fma2(acc01, xx[k], c.x);
            fma2(acc23, xx[k], c.y);
        }
        float a0, a1, a2, a3;
        unpack2(acc01, a0, a1);
        unpack2(acc23, a2, a3);
        // first-argmax semantics (ascending m)
        if (a0 > maxv) { maxv = a0; argm = 4 * mq + 0; }
        if (a1 > maxv) { maxv = a1; argm = 4 * mq + 1; }
        if (a2 > maxv) { maxv = a2; argm = 4 * mq + 2; }
        if (a3 > maxv) { maxv = a3; argm = 4 * mq + 3; }
    }
    g_assign[(size_t)bh * LPIX + l] = (unsigned char)argm;
}

// ---------------------------------------------------------------------------
// K2s: deterministic counting sort, per bh. 1024 threads (32 warps).
// ---------------------------------------------------------------------------
__global__ void __launch_bounds__(1024) k_sort() {
    GDC_WAIT();        // g_assign from k_assign
    GDC_LAUNCH();
    int bh = blockIdx.x;
    int tid = threadIdx.x;
    int warp = tid >> 5, lane = tid & 31;

    __shared__ __align__(16) unsigned char sa[LPIX];     // 4 KB
    __shared__ __align__(16) unsigned short slist[LPIX]; // 8 KB
    __shared__ int shist[32][65];          // padded: conflict-free cols
    __shared__ int scur[32][65];
    __shared__ int stot[64];
    __shared__ int soff[65];

    ((uint*)sa)[tid] = ((const uint*)(g_assign + (size_t)bh * LPIX))[tid];
    shist[warp][lane] = 0;
    shist[warp][lane + 32] = 0;
    __syncthreads();

    // ---- per-warp histogram (4 iterations of 32 pixels)
    int mloc[4];
    int base = warp * 128;
#pragma unroll
    for (int it = 0; it < 4; ++it) {
        int m = sa[base + it * 32 + lane];
        mloc[it] = m;
        unsigned int grp = __match_any_sync(0xffffffffu, m);
        int leader = __ffs(grp) - 1;
        if (lane == leader) shist[warp][m] += __popc(grp);
    }
    __syncthreads();

    // ---- warp-parallel combine: warp handles clusters {warp, warp+32}
#pragma unroll
    for (int c = 0; c < 2; c++) {
        int m = warp + c * 32;
        int v = shist[lane][m];
        int s = v;
#pragma unroll
        for (int o = 1; o < 32; o <<= 1) {
            int t = __shfl_up_sync(0xffffffffu, s, o);
            if (lane >= o) s += t;
        }
        scur[lane][m] = s - v;             // exclusive over warps
        if (lane == 31) stot[m] = s;
    }
    __syncthreads();

    // ---- exclusive prefix over 64 cluster totals (single warp)
    if (warp == 0) {
        int v0 = stot[2 * lane], v1 = stot[2 * lane + 1];
        int s = v0 + v1;
#pragma unroll
        for (int o = 1; o < 32; o <<= 1) {
            int t = __shfl_up_sync(0xffffffffu, s, o);
            if (lane >= o) s += t;
        }
        int excl = s - v0 - v1;
        soff[2 * lane]     = excl;
        soff[2 * lane + 1] = excl + v0;
        if (lane == 31) soff[64] = s;      // == LPIX
    }
    __syncthreads();

    // ---- cursors += cluster base (fully parallel)
    {
        int p0 = tid;
        scur[p0 >> 6][p0 & 63] += soff[p0 & 63];
        int p1 = tid + 1024;
        scur[p1 >> 6][p1 & 63] += soff[p1 & 63];
    }
    __syncthreads();

    // ---- stable scatter into SHARED slist (4 iterations)
    unsigned int ltmask = (1u << lane) - 1u;
#pragma unroll
    for (int it = 0; it < 4; ++it) {
        int m = mloc[it];
        unsigned int grp = __match_any_sync(0xffffffffu, m);
        int rank = __popc(grp & ltmask);
        int pos = scur[warp][m];
        slist[pos + rank] = (unsigned short)(base + it * 32 + lane);
        int leader = __ffs(grp) - 1;
        if (lane == leader) scur[warp][m] = pos + __popc(grp);
        __syncwarp();
    }
    __syncthreads();

    // ---- coalesced copy to global: 1024 threads x 8B = 8 KB
    ((uint2*)(g_sorted + (size_t)bh * LPIX))[tid] = ((const uint2*)slist)[tid];

    if (tid < 65) g_soff[bh * 65 + tid] = soff[tid];
}

// ---------------------------------------------------------------------------
// K2b: pure gather from presorted lists. Block per (bh,m), 128 threads.
// 4 warps chunk the list; 4 entries/iter -> 8 outstanding 128B loads.
// ---------------------------------------------------------------------------
__global__ void __launch_bounds__(128) k_gather(const float* __restrict__ xk,
                                                const float* __restrict__ xv,
                                                float* __restrict__ out) {
    GDC_WAIT();        // g_sorted / g_soff from k_sort
    GDC_LAUNCH();
    int blk = blockIdx.x;
    int bh = blk >> 6, m = blk & 63;
    int warp = threadIdx.x >> 5, lane = threadIdx.x & 31;

    int s0 = g_soff[bh * 65 + m];
    int n  = g_soff[bh * 65 + m + 1] - s0;
    const unsigned short* lst = g_sorted + (size_t)bh * LPIX + s0;

    const float* xkb = xk + (size_t)bh * LPIX * DIM;
    const float* xvb = xv + (size_t)bh * LPIX * DIM;

    float accK = 0.f, accV = 0.f;
    int isi = 0, isj = 0;
    int per = (n + 3) >> 2;
    int e  = warp * per;
    int e1 = min(e + per, n);
    for (; e + 3 < e1; e += 4) {
        int l0 = lst[e], l1 = lst[e + 1], l2 = lst[e + 2], l3 = lst[e + 3];
        float k0 = __ldg(xkb + l0 * 32 + lane);
        float k1 = __ldg(xkb + l1 * 32 + lane);
        float k2 = __ldg(xkb + l2 * 32 + lane);
        float k3 = __ldg(xkb + l3 * 32 + lane);
        float v0 = __ldg(xvb + l0 * 32 + lane);
        float v1 = __ldg(xvb + l1 * 32 + lane);
        float v2 = __ldg(xvb + l2 * 32 + lane);
        float v3 = __ldg(xvb + l3 * 32 + lane);
        accK += (k0 + k1) + (k2 + k3);
        accV += (v0 + v1) + (v2 + v3);
        isi += (l0 >> 6) + (l1 >> 6) + (l2 >> 6) + (l3 >> 6);
        isj += (l0 & 63) + (l1 & 63) + (l2 & 63) + (l3 & 63);
    }
    for (; e < e1; ++e) {
        int l0 = lst[e];
        accK += __ldg(xkb + l0 * 32 + lane);
        accV += __ldg(xvb + l0 * 32 + lane);
        isi += l0 >> 6;
        isj += l0 & 63;
    }

    __shared__ float sk[4][32], sv[4][32];
    __shared__ int ssi[4], ssj[4];
    sk[warp][lane] = accK;
    sv[warp][lane] = accV;
    if (lane == 0) { ssi[warp] = isi; ssj[warp] = isj; }
    __syncthreads();

    if (warp == 0) {
        float k4 = sk[0][lane] + sk[1][lane] + sk[2][lane] + sk[3][lane];
        float v4 = sv[0][lane] + sv[1][lane] + sv[2][lane] + sv[3][lane];
        float tsi = (float)(ssi[0] + ssi[1] + ssi[2] + ssi[3]);
        float tsj = (float)(ssj[0] + ssj[1] + ssj[2] + ssj[3]);
        float denom = (n > 0) ? (float)n : 1.0f;   // matches s==0 -> 1 guard

        if (lane == 0) {
            g_centers[((size_t)bh * 64 + m) * 2 + 0] = tsi / denom;
            g_centers[((size_t)bh * 64 + m) * 2 + 1] = tsj / denom;
        }
        out[131072 + ((size_t)bh * 64 + m) * 32 + lane] = v4 / denom;  // c_v
        float sq = k4 * k4;
#pragma unroll
        for (int o = 16; o > 0; o >>= 1) sq += __shfl_xor_sync(0xffffffffu, sq, o);
        float inv = 1.0f / fmaxf(sqrt_ap(sq), 1e-12f);
        out[((size_t)bh * 64 + m) * 32 + lane] = k4 * inv;             // c_q
    }
}

// ---------------------------------------------------------------------------
// K3: rpb[bh][l][m] = exp(-dist(pixel l, center[bh][m])); streaming stores
// ---------------------------------------------------------------------------
__global__ void __launch_bounds__(256) k_rpb(float* __restrict__ out) {
    GDC_WAIT();        // g_centers from k_gather
    int bh = blockIdx.y;
    __shared__ float2 sc[MM];
    if (threadIdx.x < 64)
        sc[threadIdx.x] = ((const float2*)(g_centers + (size_t)bh * 128))[threadIdx.x];
    __syncthreads();

    int pix = threadIdx.x >> 4;     // 0..15
    int mg  = threadIdx.x & 15;     // 0..15 (quad of m)
    int l = blockIdx.x * 16 + pix;
    float fi = (float)(l >> 6), fj = (float)(l & 63);
    float4 r;
#pragma unroll
    for (int q = 0; q < 4; q++) {
        float2 c = sc[mg * 4 + q];
        float dh = fi - c.x, dw = fj - c.y;
        (&r.x)[q] = __expf(-sqrt_ap(dh * dh + dw * dw));
    }
    __stcs((float4*)(out + 262144) + (size_t)bh * 65536 + (size_t)l * 16 + mg, r);
}

// ---------------------------------------------------------------------------
static inline void launch_pdl(void* fn, dim3 grid, dim3 block,
                              void** args, cudaStream_t stream) {
    cudaLaunchConfig_t cfg = {};
    cudaLaunchAttribute attr[1];
    attr[0].id = cudaLaunchAttributeProgrammaticStreamSerialization;
    attr[0].val.programmaticStreamSerializationAllowed = 1;
    cfg.gridDim = grid;
    cfg.blockDim = block;
    cfg.attrs = attr;
    cfg.numAttrs = 1;
    cfg.stream = stream;
    cudaLaunchKernelExC(&cfg, fn, args);
}

extern "C" void kernel_launch(void* const* d_in, const int* in_sizes, int n_in,
                              void* d_out, int out_size) {
    const float* xk    = (const float*)d_in[0];
    const float* xv    = (const float*)d_in[1];
    const float* scale = (const float*)d_in[2];
    float* out = (float*)d_out;

    k_init<<<4352, 256>>>(xk);

    {
        void* args[] = { (void*)&xk, (void*)&scale };
        launch_pdl((void*)k_assign, dim3(16, 64), dim3(256), args, 0);
    }
    {
        void* args[] = {};
        launch_pdl((void*)k_sort, dim3(64), dim3(1024), args, 0);
    }
    {
        void* args[] = { (void*)&xk, (void*)&xv, (void*)&out };
        launch_pdl((void*)k_gather, dim3(4096), dim3(128), args, 0);
    }
    {
        void* args[] = { (void*)&out };
        launch_pdl((void*)k_rpb, dim3(256, 64), dim3(256), args, 0);
    }
}